// round 7
// baseline (speedup 1.0000x reference)
#include <cuda_runtime.h>
#include <cstdint>
#include <math_constants.h>

#define N_MAX 65536
#define M_IND 1024
#define KNN 16
#define BUFCAP 192
#define NSU 136   // lower-triangular 16x16 tile blocks for su

// Scratch (static device globals — no allocation allowed)
__device__ unsigned g_idx[N_MAX * KNN];        // selected neighbor indices
__device__ float    g_Su[M_IND * M_IND];       // Su = Lu Lu^T

// ---------------------------------------------------------------------------
// Fused kernel: blocks [0, NSU) compute Su = Lu Lu^T tiles (64x64, 4x4 micro),
// blocks [NSU, NSU+ceil(N/256)) each do exact 16-NN for 256 points.
// Fusion lets the two independent phases share the GPU (graph stream is serial).
// ---------------------------------------------------------------------------
__global__ void fused_kernel(const float* __restrict__ X,
                             const float* __restrict__ Z,
                             const float* __restrict__ raw, int N) {
    __shared__ float4 zs[M_IND];     // topk path (16 KB)
    __shared__ float At[16][68];     // su path (4.3 KB)
    __shared__ float Bt[16][68];     // su path (4.3 KB)

    if (blockIdx.x < NSU) {
        // ================= su part =================
        int s = blockIdx.x;
        int bi = (int)((__fsqrt_rn(8.0f * (float)s + 1.0f) - 1.0f) * 0.5f);
        while ((bi + 1) * (bi + 2) / 2 <= s) bi++;
        while (bi * (bi + 1) / 2 > s) bi--;
        int bj = s - bi * (bi + 1) / 2;    // 0 <= bj <= bi

        int tid = threadIdx.x;           // 256 threads
        int tx = tid & 15, ty = tid >> 4;
        int lr = tid >> 2;
        int lk = (tid & 3) << 2;
        int rA = bi << 6, rB = bj << 6;
        int nk = (bj + 1) << 6;

        float acc[4][4];
#pragma unroll
        for (int u = 0; u < 4; u++)
#pragma unroll
            for (int v = 0; v < 4; v++) acc[u][v] = 0.0f;

        for (int kc = 0; kc < nk; kc += 16) {
            int ga = rA + lr;
            float4 va = *(const float4*)(raw + (size_t)ga * M_IND + kc + lk);
            int gb = rB + lr;
            float4 vb = *(const float4*)(raw + (size_t)gb * M_IND + kc + lk);
            float a4[4] = {va.x, va.y, va.z, va.w};
            float b4[4] = {vb.x, vb.y, vb.z, vb.w};
#pragma unroll
            for (int u = 0; u < 4; u++) {
                int gc = kc + lk + u;
                float x = a4[u];
                At[lk + u][lr] = (gc < ga) ? x : ((gc == ga) ? expf(x) : 0.0f);
                float y = b4[u];
                Bt[lk + u][lr] = (gc < gb) ? y : ((gc == gb) ? expf(y) : 0.0f);
            }
            __syncthreads();
#pragma unroll
            for (int kk = 0; kk < 16; kk++) {
                float4 a = *(const float4*)&At[kk][ty << 2];
                float4 b = *(const float4*)&Bt[kk][tx << 2];
                float aa[4] = {a.x, a.y, a.z, a.w};
                float bb[4] = {b.x, b.y, b.z, b.w};
#pragma unroll
                for (int u = 0; u < 4; u++)
#pragma unroll
                    for (int v = 0; v < 4; v++)
                        acc[u][v] = fmaf(aa[u], bb[v], acc[u][v]);
            }
            __syncthreads();
        }
#pragma unroll
        for (int u = 0; u < 4; u++)
#pragma unroll
            for (int v = 0; v < 4; v++) {
                int gi = rA + (ty << 2) + u;
                int gj = rB + (tx << 2) + v;
                g_Su[(size_t)gi * M_IND + gj] = acc[u][v];
                g_Su[(size_t)gj * M_IND + gi] = acc[u][v];
            }
        return;
    }

    // ================= topk part (exact 16-NN, branchless selection) =======
    for (int t = threadIdx.x; t < M_IND; t += blockDim.x) {
        float a = Z[3 * t], b = Z[3 * t + 1], c = Z[3 * t + 2];
        zs[t] = make_float4(a, b, c, fmaf(a, a, fmaf(b, b, c * c)));
    }
    __syncthreads();
    int p = (blockIdx.x - NSU) * blockDim.x + threadIdx.x;
    if (p >= N) return;
    float x0 = X[3 * p], x1 = X[3 * p + 1], x2 = X[3 * p + 2];
    float xs = fmaf(x0, x0, fmaf(x1, x1, x2 * x2));
    float n0 = -2.0f * x0, n1 = -2.0f * x1, n2 = -2.0f * x2;

    // ---- P1: stride-8 sample, branchless sorted bubble -> exact sample 16th
    float ks[KNN];
#pragma unroll
    for (int s = 0; s < KNN; s++) ks[s] = CUDART_INF_F;
#pragma unroll 2
    for (int i = 0; i < M_IND; i += 8) {
        float4 z = zs[i];
        float t = fmaxf(fmaf(n0, z.x, fmaf(n1, z.y, fmaf(n2, z.z, xs + z.w))), 0.0f);
#pragma unroll
        for (int s = 0; s < KNN; s++) {
            float lo = fminf(ks[s], t);
            float hi = fmaxf(ks[s], t);
            ks[s] = lo; t = hi;
        }
    }
    float T0 = ks[KNN - 1];   // exact sample 16th-smallest d2 (threshold)

    // ---- P2: predicated buffering of candidates {d <= T0} (idx + d) ----
    unsigned short buf[BUFCAP];
    float bufd[BUFCAP];
    int c = 0;
#pragma unroll 4
    for (int i = 0; i < M_IND; i++) {
        float4 z = zs[i];
        float d = fmaxf(fmaf(n0, z.x, fmaf(n1, z.y, fmaf(n2, z.z, xs + z.w))), 0.0f);
        bool take = (d <= T0);
        int w = c < BUFCAP ? c : BUFCAP - 1;
        if (take) { buf[w] = (unsigned short)i; bufd[w] = d; }
        c += take ? 1 : 0;
    }

    unsigned e16[KNN];
    if (c <= BUFCAP) {
        // ---- P3: branchless bubble over candidates -> exact 16th value T* --
        float ks3[KNN];
#pragma unroll
        for (int s = 0; s < KNN; s++) ks3[s] = CUDART_INF_F;
#pragma unroll 2
        for (int j = 0; j < c; j++) {
            float t = bufd[j];
#pragma unroll
            for (int s = 0; s < KNN; s++) {
                float lo = fminf(ks3[s], t);
                float hi = fmaxf(ks3[s], t);
                ks3[s] = lo; t = hi;
            }
        }
        float Tstar = ks3[KNN - 1];

        // ---- P4: emit d < T*, then ties d == T* in ascending-i order ----
        int cnt = 0;
        for (int j = 0; j < c; j++) {
            float d = bufd[j];
            if (d < Tstar && cnt < KNN) { e16[cnt] = buf[j]; cnt++; }
        }
        for (int j = 0; j < c; j++) {
            float d = bufd[j];
            if (d == Tstar && cnt < KNN) { e16[cnt] = buf[j]; cnt++; }
        }
    } else {
        // Fallback (pathological): full exact u64 replace-max scan
        unsigned long long ks2[KNN];
#pragma unroll
        for (int s = 0; s < KNN; s++)
            ks2[s] = 0xFFFFFFFF00000000ull | (unsigned)s;
        unsigned long long kmax2 = 0xFFFFFFFF0000000Full;
        for (int i = 0; i < M_IND; i++) {
            float4 z = zs[i];
            float d = fmaxf(fmaf(n0, z.x, fmaf(n1, z.y, fmaf(n2, z.z, xs + z.w))), 0.0f);
            unsigned long long key =
                ((unsigned long long)__float_as_uint(d) << 32) | (unsigned)i;
            if (key < kmax2) {
#pragma unroll
                for (int s = 0; s < KNN; s++) ks2[s] = (ks2[s] == kmax2) ? key : ks2[s];
                unsigned long long m = ks2[0];
#pragma unroll
                for (int s = 1; s < KNN; s++) m = max(m, ks2[s]);
                kmax2 = m;
            }
        }
#pragma unroll
        for (int s = 0; s < KNN; s++) e16[s] = (unsigned)(ks2[s] & 0xFFFFFFFFu);
    }

    uint4* o = (uint4*)(g_idx + (size_t)p * KNN);
    o[0] = make_uint4(e16[0], e16[1], e16[2], e16[3]);
    o[1] = make_uint4(e16[4], e16[5], e16[6], e16[7]);
    o[2] = make_uint4(e16[8], e16[9], e16[10], e16[11]);
    o[3] = make_uint4(e16[12], e16[13], e16[14], e16[15]);
}

// ---------------------------------------------------------------------------
// Kernel 2: half-warp per point, register-resident fp32 Gauss-Jordan.
// ---------------------------------------------------------------------------
__global__ void solve_kernel(const float* __restrict__ X,
                             const float* __restrict__ Z,
                             const float* __restrict__ mu,
                             float* __restrict__ out, int N) {
    const unsigned FULL = 0xFFFFFFFFu;
    int lane = threadIdx.x & 31;
    int half = lane >> 4;
    int l = lane & 15;
    int p = (blockIdx.x << 4) + ((threadIdx.x >> 5) << 1) + half;
    int pc = p < N ? p : N - 1;

    float x0 = X[3 * pc], x1 = X[3 * pc + 1], x2 = X[3 * pc + 2];
    float xs = fmaf(x0, x0, fmaf(x1, x1, x2 * x2));

    unsigned idxv = g_idx[(size_t)pc * KNN + l];
    float zx = Z[3 * idxv], zy = Z[3 * idxv + 1], zz = Z[3 * idxv + 2];
    float z2 = fmaf(zx, zx, fmaf(zy, zy, zz * zz));
    float d2r = fmaxf(xs + z2 - 2.0f * fmaf(x0, zx, fmaf(x1, zy, x2 * zz)), 0.0f);
    float muv = mu[idxv];

    float a[17];
    a[16] = expf(-0.5f * d2r);   // rhs = lKxz

#pragma unroll
    for (int i = 0; i < 16; i++) {
        float zxi = __shfl_sync(FULL, zx, i, 16);
        float zyi = __shfl_sync(FULL, zy, i, 16);
        float zzi = __shfl_sync(FULL, zz, i, 16);
        float dx = zxi - zx, dy = zyi - zy, dz = zzi - zz;
        float d2 = fmaf(dx, dx, fmaf(dy, dy, dz * dz));
        a[i] = (i == l) ? (1.0f + 2e-4f) : expf(-0.5f * d2);
    }

#pragma unroll
    for (int k = 0; k < 16; k++) {
        float piv = __shfl_sync(FULL, a[k], k, 16);
        float rp = 1.0f / piv;
        float f = (l == k) ? 0.0f : a[k] * rp;
#pragma unroll
        for (int cc = k + 1; cc <= 16; cc++) {
            float bc = __shfl_sync(FULL, a[cc], k, 16);
            a[cc] = fmaf(-f, bc, a[cc]);
        }
    }
    float diag = a[0];
#pragma unroll
    for (int cc = 1; cc < 16; cc++) if (l == cc) diag = a[cc];
    float Wv = a[16] / diag;

    float acc = 0.0f;
#pragma unroll
    for (int i = 0; i < 16; i++) {
        float Wi = __shfl_sync(FULL, Wv, i, 16);
        unsigned ia = __shfl_sync(FULL, idxv, i, 16);
        float su = g_Su[(size_t)ia * M_IND + idxv];
        float zxi = __shfl_sync(FULL, zx, i, 16);
        float zyi = __shfl_sync(FULL, zy, i, 16);
        float zzi = __shfl_sync(FULL, zz, i, 16);
        float dx = zxi - zx, dy = zyi - zy, dz = zzi - zz;
        float d2 = fmaf(dx, dx, fmaf(dy, dy, dz * dz));
        float kv = (i == l) ? 1.0001f : expf(-0.5f * d2);
        acc = fmaf(Wi * Wv, su - kv, acc);
    }
    float mpart = Wv * muv;
#pragma unroll
    for (int o = 8; o > 0; o >>= 1) {
        acc   += __shfl_xor_sync(FULL, acc, o, 16);
        mpart += __shfl_xor_sync(FULL, mpart, o, 16);
    }
    if (l == 0 && p < N) {
        out[p] = mpart;                                // mean
        float cov = 1.0f + acc;
        out[N + p] = sqrtf(fmaxf(cov, 0.05f));         // std
    }
}

// ---------------------------------------------------------------------------
extern "C" void kernel_launch(void* const* d_in, const int* in_sizes, int n_in,
                              void* d_out, int out_size) {
    const float* X      = (const float*)d_in[0];
    const float* Z      = (const float*)d_in[1];
    const float* Lu_raw = (const float*)d_in[2];
    const float* mu     = (const float*)d_in[3];
    float* out = (float*)d_out;
    int N = in_sizes[0] / 3;

    int topk_blocks = (N + 255) / 256;
    fused_kernel<<<NSU + topk_blocks, 256>>>(X, Z, Lu_raw, N);
    solve_kernel<<<(N + 15) / 16, 256>>>(X, Z, mu, out, N);
}

// round 8
// speedup vs baseline: 1.5548x; 1.5548x over previous
#include <cuda_runtime.h>
#include <cstdint>
#include <math_constants.h>

#define N_MAX 65536
#define M_IND 1024
#define KNN 16
#define BUFCAP 192
#define SU_NB 32
#define SU_BLOCKS (SU_NB * (SU_NB + 1) / 2)   // 528

// Scratch (static device globals — no allocation allowed)
__device__ unsigned g_idx[N_MAX * KNN];
__device__ float    g_Su[M_IND * M_IND];

// ---------------------------------------------------------------------------
// Kernel 1: Su = Lu Lu^T. 32x32 tiles, 528 triangular blocks, 256 thr, 2x2.
// ---------------------------------------------------------------------------
__global__ void su_kernel(const float* __restrict__ raw) {
    __shared__ float At[32][33];
    __shared__ float Bt[32][33];
    int s = blockIdx.x;
    int bi = (int)((__fsqrt_rn(8.0f * (float)s + 1.0f) - 1.0f) * 0.5f);
    while ((bi + 1) * (bi + 2) / 2 <= s) bi++;
    while (bi * (bi + 1) / 2 > s) bi--;
    int bj = s - bi * (bi + 1) / 2;          // bj <= bi

    int tid = threadIdx.x;
    int tx = tid & 15, ty = tid >> 4;
    int lr = tid >> 3;                       // 0..31 row in tile
    int lc = (tid & 7) << 2;                 // k col group of 4
    int rA = bi * 32, rB = bj * 32;
    int nk = (bj + 1) * 32;                  // k <= min(i,j); rest is 0

    float acc00 = 0.f, acc01 = 0.f, acc10 = 0.f, acc11 = 0.f;
    for (int kc = 0; kc < nk; kc += 32) {
        int ga = rA + lr;
        float4 va = *(const float4*)(raw + (size_t)ga * M_IND + kc + lc);
        int gb = rB + lr;
        float4 vb = *(const float4*)(raw + (size_t)gb * M_IND + kc + lc);
        float a4[4] = {va.x, va.y, va.z, va.w};
        float b4[4] = {vb.x, vb.y, vb.z, vb.w};
#pragma unroll
        for (int u = 0; u < 4; u++) {
            int gc = kc + lc + u;
            float x = a4[u];
            At[lc + u][lr] = (gc < ga) ? x : ((gc == ga) ? expf(x) : 0.0f);
            float y = b4[u];
            Bt[lc + u][lr] = (gc < gb) ? y : ((gc == gb) ? expf(y) : 0.0f);
        }
        __syncthreads();
#pragma unroll
        for (int kk = 0; kk < 32; kk++) {
            float a0 = At[kk][ty * 2], a1 = At[kk][ty * 2 + 1];
            float b0 = Bt[kk][tx * 2], b1 = Bt[kk][tx * 2 + 1];
            acc00 = fmaf(a0, b0, acc00);
            acc01 = fmaf(a0, b1, acc01);
            acc10 = fmaf(a1, b0, acc10);
            acc11 = fmaf(a1, b1, acc11);
        }
        __syncthreads();
    }
    int gi0 = rA + ty * 2, gj0 = rB + tx * 2;
    g_Su[(size_t)gi0 * M_IND + gj0]           = acc00;
    g_Su[(size_t)gi0 * M_IND + gj0 + 1]       = acc01;
    g_Su[(size_t)(gi0 + 1) * M_IND + gj0]     = acc10;
    g_Su[(size_t)(gi0 + 1) * M_IND + gj0 + 1] = acc11;
    g_Su[(size_t)gj0 * M_IND + gi0]           = acc00;
    g_Su[(size_t)(gj0 + 1) * M_IND + gi0]     = acc01;
    g_Su[(size_t)gj0 * M_IND + gi0 + 1]       = acc10;
    g_Su[(size_t)(gj0 + 1) * M_IND + gi0 + 1] = acc11;
}

// ---------------------------------------------------------------------------
// Kernel 2: exact 16-NN, latency-optimized branchless selection.
// ---------------------------------------------------------------------------
__global__ void topk_kernel(const float* __restrict__ X,
                            const float* __restrict__ Z, int N) {
    __shared__ float4 zs[M_IND];
    for (int t = threadIdx.x; t < M_IND; t += blockDim.x) {
        float a = Z[3 * t], b = Z[3 * t + 1], c = Z[3 * t + 2];
        zs[t] = make_float4(a, b, c, fmaf(a, a, fmaf(b, b, c * c)));
    }
    __syncthreads();
    int p = blockIdx.x * blockDim.x + threadIdx.x;
    if (p >= N) return;
    float x0 = X[3 * p], x1 = X[3 * p + 1], x2 = X[3 * p + 2];
    float xs = fmaf(x0, x0, fmaf(x1, x1, x2 * x2));
    float n0 = -2.0f * x0, n1 = -2.0f * x1, n2 = -2.0f * x2;

#define DIST(Zv) fmaxf(fmaf(n0, (Zv).x, fmaf(n1, (Zv).y, fmaf(n2, (Zv).z, xs + (Zv).w))), 0.0f)

    // ---- P1: stride-8 sample (128), 4-way interleaved bubble ----
    float ks[KNN];
#pragma unroll
    for (int s = 0; s < KNN; s++) ks[s] = CUDART_INF_F;
    for (int i = 0; i < M_IND; i += 32) {
        float4 z0 = zs[i], z1 = zs[i + 8], z2v = zs[i + 16], z3 = zs[i + 24];
        float t0 = DIST(z0), t1 = DIST(z1), t2 = DIST(z2v), t3 = DIST(z3);
#pragma unroll
        for (int s = 0; s < KNN; s++) {
            float a = ks[s];
            float m0 = fminf(a, t0);  t0 = fmaxf(a, t0);
            float m1 = fminf(m0, t1); t1 = fmaxf(m0, t1);
            float m2 = fminf(m1, t2); t2 = fmaxf(m1, t2);
            float m3 = fminf(m2, t3); t3 = fmaxf(m2, t3);
            ks[s] = m3;
        }
    }
    float T0 = ks[KNN - 1];      // exact sample 16th-smallest (valid threshold)

    // ---- P2: predicated u16 buffering, tree-prefix write indices ----
    unsigned short buf[BUFCAP];
    int c = 0;
    for (int i = 0; i < M_IND; i += 8) {
        int t[8];
        float d[8];
#pragma unroll
        for (int u = 0; u < 8; u++) {
            float4 z = zs[i + u];
            d[u] = DIST(z);
            t[u] = d[u] <= T0;
        }
        int s01 = t[0] + t[1], s23 = t[2] + t[3];
        int s45 = t[4] + t[5], s67 = t[6] + t[7];
        int s03 = s01 + s23, s47 = s45 + s67;
        int pre[8];
        pre[0] = 0;        pre[1] = t[0];
        pre[2] = s01;      pre[3] = s01 + t[2];
        pre[4] = s03;      pre[5] = s03 + t[4];
        pre[6] = s03 + s45; pre[7] = s03 + s45 + t[6];
#pragma unroll
        for (int u = 0; u < 8; u++) {
            int w = c + pre[u];
            w = w < BUFCAP ? w : BUFCAP - 1;
            if (t[u]) buf[w] = (unsigned short)(i + u);
        }
        c += s03 + s47;
    }

    unsigned base = (unsigned)p * KNN;
    if (c <= BUFCAP) {
        // ---- P3: exact 16th among candidates (2-way interleaved bubble) ----
        float ks3[KNN];
#pragma unroll
        for (int s = 0; s < KNN; s++) ks3[s] = CUDART_INF_F;
        int c2 = c & ~1;
        for (int j = 0; j < c2; j += 2) {
            float4 za = zs[buf[j]], zb = zs[buf[j + 1]];
            float ta = DIST(za), tb = DIST(zb);
#pragma unroll
            for (int s = 0; s < KNN; s++) {
                float a = ks3[s];
                float m0 = fminf(a, ta);  ta = fmaxf(a, ta);
                float m1 = fminf(m0, tb); tb = fmaxf(m0, tb);
                ks3[s] = m1;
            }
        }
        if (c & 1) {
            float4 za = zs[buf[c - 1]];
            float ta = DIST(za);
#pragma unroll
            for (int s = 0; s < KNN; s++) {
                float a = ks3[s];
                ks3[s] = fminf(a, ta); ta = fmaxf(a, ta);
            }
        }
        float Tstar = ks3[KNN - 1];

        // ---- P4: predicated direct-STG emission (d<T*, then ties d==T*) ----
        int cnt = 0;
        for (int j = 0; j < c; j++) {
            int i = buf[j];
            float4 z = zs[i];
            float dd = DIST(z);
            bool em = (dd < Tstar) & (cnt < KNN);
            if (em) g_idx[base + cnt] = (unsigned)i;
            cnt += em;
        }
        for (int j = 0; j < c; j++) {
            int i = buf[j];
            float4 z = zs[i];
            float dd = DIST(z);
            bool em = (dd == Tstar) & (cnt < KNN);
            if (em) g_idx[base + cnt] = (unsigned)i;
            cnt += em;
        }
    } else {
        // Fallback: full exact u64 replace-max (pathological only)
        unsigned long long ks2[KNN];
#pragma unroll
        for (int s = 0; s < KNN; s++)
            ks2[s] = 0xFFFFFFFF00000000ull | (unsigned)s;
        unsigned long long kmax2 = 0xFFFFFFFF0000000Full;
        for (int i = 0; i < M_IND; i++) {
            float4 z = zs[i];
            float dd = DIST(z);
            unsigned long long key =
                ((unsigned long long)__float_as_uint(dd) << 32) | (unsigned)i;
            if (key < kmax2) {
#pragma unroll
                for (int s = 0; s < KNN; s++) ks2[s] = (ks2[s] == kmax2) ? key : ks2[s];
                unsigned long long m = ks2[0];
#pragma unroll
                for (int s = 1; s < KNN; s++) m = max(m, ks2[s]);
                kmax2 = m;
            }
        }
#pragma unroll
        for (int s = 0; s < KNN; s++)
            g_idx[base + s] = (unsigned)(ks2[s] & 0xFFFFFFFFu);
    }
#undef DIST
}

// ---------------------------------------------------------------------------
// Kernel 3: half-warp per point, register fp32 Gauss-Jordan; symmetric cov
// (i<l pairs x2 + diagonal), inactive-lane Su loads redirected to a
// broadcast line (no divergence, half the gather wavefronts).
// ---------------------------------------------------------------------------
__global__ void solve_kernel(const float* __restrict__ X,
                             const float* __restrict__ Z,
                             const float* __restrict__ mu,
                             float* __restrict__ out, int N) {
    const unsigned FULL = 0xFFFFFFFFu;
    int lane = threadIdx.x & 31;
    int half = lane >> 4;
    int l = lane & 15;
    int p = (blockIdx.x << 4) + ((threadIdx.x >> 5) << 1) + half;
    int pc = p < N ? p : N - 1;

    float x0 = X[3 * pc], x1 = X[3 * pc + 1], x2 = X[3 * pc + 2];
    float xs = fmaf(x0, x0, fmaf(x1, x1, x2 * x2));

    unsigned idxv = g_idx[(size_t)pc * KNN + l];
    float zx = Z[3 * idxv], zy = Z[3 * idxv + 1], zz = Z[3 * idxv + 2];
    float z2 = fmaf(zx, zx, fmaf(zy, zy, zz * zz));
    float d2r = fmaxf(xs + z2 - 2.0f * fmaf(x0, zx, fmaf(x1, zy, x2 * zz)), 0.0f);
    float muv = mu[idxv];

    float a[17];
    a[16] = expf(-0.5f * d2r);   // rhs = lKxz

#pragma unroll
    for (int i = 0; i < 16; i++) {
        float zxi = __shfl_sync(FULL, zx, i, 16);
        float zyi = __shfl_sync(FULL, zy, i, 16);
        float zzi = __shfl_sync(FULL, zz, i, 16);
        float dx = zxi - zx, dy = zyi - zy, dz = zzi - zz;
        float d2 = fmaf(dx, dx, fmaf(dy, dy, dz * dz));
        a[i] = (i == l) ? (1.0f + 2e-4f) : expf(-0.5f * d2);
    }

#pragma unroll
    for (int k = 0; k < 16; k++) {
        float piv = __shfl_sync(FULL, a[k], k, 16);
        float rp = 1.0f / piv;
        float f = (l == k) ? 0.0f : a[k] * rp;
#pragma unroll
        for (int cc = k + 1; cc <= 16; cc++) {
            float bc = __shfl_sync(FULL, a[cc], k, 16);
            a[cc] = fmaf(-f, bc, a[cc]);
        }
    }
    float diag = a[0];
#pragma unroll
    for (int cc = 1; cc < 16; cc++) if (l == cc) diag = a[cc];
    float Wv = a[16] / diag;

    // cov = 1 + Wv^2 (su_ll - (1+1e-4)) + 2 * sum_{i<l} Wi Wv (su_il - kv_il)
    float acc = 0.0f;
#pragma unroll
    for (int i = 0; i < 15; i++) {
        float Wi = __shfl_sync(FULL, Wv, i, 16);
        unsigned ia = __shfl_sync(FULL, idxv, i, 16);
        float zxi = __shfl_sync(FULL, zx, i, 16);
        float zyi = __shfl_sync(FULL, zy, i, 16);
        float zzi = __shfl_sync(FULL, zz, i, 16);
        bool keep = (i < l);
        const float* addr = keep ? (g_Su + (size_t)ia * M_IND + idxv) : g_Su;
        float su = __ldg(addr);
        float dx = zxi - zx, dy = zyi - zy, dz = zzi - zz;
        float d2 = fmaf(dx, dx, fmaf(dy, dy, dz * dz));
        float kv = expf(-0.5f * d2);
        float coef = keep ? 2.0f * Wi * Wv : 0.0f;
        acc = fmaf(coef, su - kv, acc);
    }
    {
        float su_ll = __ldg(g_Su + (size_t)idxv * M_IND + idxv);
        acc = fmaf(Wv * Wv, su_ll - 1.0001f, acc);
    }
    float mpart = Wv * muv;
#pragma unroll
    for (int o = 8; o > 0; o >>= 1) {
        acc   += __shfl_xor_sync(FULL, acc, o, 16);
        mpart += __shfl_xor_sync(FULL, mpart, o, 16);
    }
    if (l == 0 && p < N) {
        out[p] = mpart;                                // mean
        float cov = 1.0f + acc;
        out[N + p] = sqrtf(fmaxf(cov, 0.05f));         // std
    }
}

// ---------------------------------------------------------------------------
extern "C" void kernel_launch(void* const* d_in, const int* in_sizes, int n_in,
                              void* d_out, int out_size) {
    const float* X      = (const float*)d_in[0];
    const float* Z      = (const float*)d_in[1];
    const float* Lu_raw = (const float*)d_in[2];
    const float* mu     = (const float*)d_in[3];
    float* out = (float*)d_out;
    int N = in_sizes[0] / 3;

    topk_kernel<<<(N + 127) / 128, 128>>>(X, Z, N);
    su_kernel<<<SU_BLOCKS, 256>>>(Lu_raw);
    solve_kernel<<<(N + 15) / 16, 256>>>(X, Z, mu, out, N);
}